// round 4
// baseline (speedup 1.0000x reference)
#include <cuda_runtime.h>

#define NODES 336
#define NPC   8192
#define NUMCASE 2048
#define MIU_F 1.9e-05f
#define ALPHA_F 0.10471975511965977f   // 6*pi/180
#define QCOEF_F 73830.75f              // 0.5*1.225*ACOUSTIC^2
#define FULL 0xffffffffu

// Warp-per-case. Lane l owns nodes j = l + 32k, k = 0..10 (k=10 only for l<16).
// Neighbor node j+1 lives at (lane+1, reg k), except lane31 -> (lane0, reg k+1),
// and the circular wrap node335->node0 is (lane15,k=10) -> (lane0, reg 0).
__global__ __launch_bounds__(128) void dyn_kernel(
    const float* __restrict__ coords,
    const float* __restrict__ fields,
    const float* __restrict__ design,
    float2* __restrict__ out)
{
    const int warp = threadIdx.x >> 5;
    const int l = threadIdx.x & 31;
    const int c = blockIdx.x * 4 + warp;
    const int base = c * NPC;

    float n0x[11], n0y[11], ptv[11], f1u[11], f1v[11];
    float tau[11], Txa[11], Tya[11], delta[11];
    float d3 = 0.f, d4 = 0.f;

    const float2* cf2 = (const float2*)coords;
    const float4* ff4 = (const float4*)fields;

    // ---- Phase 0: front-batched loads; delta consumed from n1 immediately ----
    #pragma unroll
    for (int k = 0; k < 11; k++) {
        const int j = l + 32 * k;
        const bool v = (k < 10) || (l < 16);
        if (v) {
            float2 a = cf2[base + j];
            float2 b = cf2[base + NODES + j];
            float4 f1 = ff4[base + NODES + j];
            n0x[k] = a.x; n0y[k] = a.y;
            f1u[k] = f1.z; f1v[k] = f1.w;
            ptv[k] = fields[4 * (base + j)];       // f0[:, :, 0]
            d3 += design[5 * (base + j) + 3];
            d4 += design[5 * (base + j) + 4];
            float dx = b.x - a.x, dy = b.y - a.y;
            delta[k] = sqrtf(dx * dx + dy * dy);
        } else {
            n0x[k] = 0.f; n0y[k] = 0.f; f1u[k] = 0.f; f1v[k] = 0.f;
            ptv[k] = 0.f; delta[k] = 1.f;
        }
    }

    // ---- Phase 1: T and tau via neighbor shuffles (no smem, no barriers) ----
    #pragma unroll
    for (int k = 0; k < 11; k++) {
        float nnx = __shfl_sync(FULL, n0x[k], (l + 1) & 31);
        float nny = __shfl_sync(FULL, n0y[k], (l + 1) & 31);
        float wx, wy; int wl;
        if (k < 10) { wx = __shfl_sync(FULL, n0x[k + 1], 0);
                      wy = __shfl_sync(FULL, n0y[k + 1], 0); wl = 31; }
        else        { wx = __shfl_sync(FULL, n0x[0], 0);
                      wy = __shfl_sync(FULL, n0y[0], 0); wl = 15; }
        if (l == wl) { nnx = wx; nny = wy; }
        float tx = nnx - n0x[k], ty = nny - n0y[k];
        Txa[k] = tx; Tya[k] = ty;
        float tn = sqrtf(tx * tx + ty * ty);
        float du = (f1u[k] * tx + f1v[k] * ty) / tn;
        tau[k] = MIU_F * du / delta[k];
    }

    // ---- Phase 2: forces, tau neighbor via the same shuffle pattern ----
    float Fx = 0.f, Fy = 0.f;
    #pragma unroll
    for (int k = 0; k < 11; k++) {
        float tn1 = __shfl_sync(FULL, tau[k], (l + 1) & 31);
        float w; int wl;
        if (k < 10) { w = __shfl_sync(FULL, tau[k + 1], 0); wl = 31; }
        else        { w = __shfl_sync(FULL, tau[0], 0);     wl = 15; }
        if (l == wl) tn1 = w;
        const bool v = (k < 10) || (l < 16);
        if (v) {
            float ta = 0.5f * (tau[k] + tn1);
            // -Px = -pt*T.y ; -Py = +pt*T.x ; +50*tau_ave*T
            Fx += -ptv[k] * Tya[k] + 50.f * ta * Txa[k];
            Fy +=  ptv[k] * Txa[k] + 50.f * ta * Tya[k];
        }
    }

    // ---- Warp reduction + epilogue (lane 0) ----
    #pragma unroll
    for (int off = 16; off; off >>= 1) {
        Fx += __shfl_down_sync(FULL, Fx, off);
        Fy += __shfl_down_sync(FULL, Fy, off);
        d3 += __shfl_down_sync(FULL, d3, off);
        d4 += __shfl_down_sync(FULL, d4, off);
    }
    if (l == 0) {
        float Ma = d3 * (0.3f / (float)NODES) + 0.3f;
        float af = d4 * (ALPHA_F / (float)NODES);
        float ca = cosf(af), sa = sinf(af);
        float Fxn = Fx * ca + Fy * sa;
        float Fyn = Fy * ca - Fxn * sa;   // reference uses Fx_new here (literal)
        float q = QCOEF_F * Ma * Ma;
        out[c] = make_float2(Fxn / q, Fyn / q);
    }
}

extern "C" void kernel_launch(void* const* d_in, const int* in_sizes, int n_in,
                              void* d_out, int out_size) {
    // metadata order: batch(int32), coords(f32), fields(f32), design(f32), num_case, nodes_num
    const float* coords = (const float*)d_in[1];
    const float* fields = (const float*)d_in[2];
    const float* design = (const float*)d_in[3];
    float2* out = (float2*)d_out;
    dyn_kernel<<<NUMCASE / 4, 128>>>(coords, fields, design, out);
}

// round 5
// speedup vs baseline: 1.0698x; 1.0698x over previous
#include <cuda_runtime.h>

#define NODES 336
#define NPC   8192
#define NUMCASE 2048
#define MIU_F 1.9e-05f
#define ALPHA_F 0.10471975511965977f   // 6*pi/180
#define QCOEF_F 73830.75f              // 0.5*1.225*ACOUSTIC^2
#define FULL 0xffffffffu

__global__ __launch_bounds__(128, 12) void dyn_kernel(
    const float* __restrict__ coords,
    const float* __restrict__ fields,
    const float* __restrict__ design,
    float2* __restrict__ out)
{
    const int c = blockIdx.x;
    const int base = c * NPC;
    const int t = threadIdx.x;

    __shared__ float2 s_n0[NODES];
    __shared__ float2 s_f1[NODES];   // (u, v)
    __shared__ float  s_dl[NODES];   // delta
    __shared__ float  s_red[4][4];

    // thread t handles nodes t, t+128, t+256 (last only for t<80)
    float2 n0[3];
    float pt[3];
    float d3 = 0.f, d4 = 0.f;

    const float2* cf2 = (const float2*)coords;
    const float4* ff4 = (const float4*)fields;

    // ---- Phase 0: front-batched loads, stage stencil data in smem ----
    #pragma unroll
    for (int k = 0; k < 3; k++) {
        int j = t + k * 128;
        bool valid = (k < 2) || (t < NODES - 256);
        if (valid) {
            n0[k] = cf2[base + j];
            float2 b = cf2[base + NODES + j];
            float4 f1 = ff4[base + NODES + j];
            pt[k] = fields[4 * (base + j)];          // f0[:, :, 0]
            d3 += design[5 * (base + j) + 3];
            d4 += design[5 * (base + j) + 4];
            s_n0[j] = n0[k];
            s_f1[j] = make_float2(f1.z, f1.w);
            float dx = b.x - n0[k].x, dy = b.y - n0[k].y;
            s_dl[j] = sqrtf(dx * dx + dy * dy);
        }
    }
    __syncthreads();

    // ---- Phase 1: compute tau[j] and tau[j+1] locally, then forces ----
    float Fx = 0.f, Fy = 0.f;
    #pragma unroll
    for (int k = 0; k < 3; k++) {
        int j = t + k * 128;
        bool valid = (k < 2) || (t < NODES - 256);
        if (valid) {
            int jp  = (j + 1 == NODES) ? 0 : j + 1;
            int jpp = (jp + 1 == NODES) ? 0 : jp + 1;
            float2 a  = n0[k];
            float2 b  = s_n0[jp];
            float2 cn = s_n0[jpp];
            // tau at j
            float tx = b.x - a.x, ty = b.y - a.y;
            float tn = sqrtf(tx * tx + ty * ty);
            float2 f = s_f1[j];
            float tau0 = MIU_F * ((f.x * tx + f.y * ty) / tn) / s_dl[j];
            // tau at j+1
            float tx1 = cn.x - b.x, ty1 = cn.y - b.y;
            float tn1 = sqrtf(tx1 * tx1 + ty1 * ty1);
            float2 f1n = s_f1[jp];
            float tau1 = MIU_F * ((f1n.x * tx1 + f1n.y * ty1) / tn1) / s_dl[jp];

            float ta = 0.5f * (tau0 + tau1);
            // -Px = -pt*T.y ; -Py = +pt*T.x ; +50*tau_ave*T
            Fx += -pt[k] * ty + 50.f * ta * tx;
            Fy +=  pt[k] * tx + 50.f * ta * ty;
        }
    }

    // ---- Block reduction over 4 warps ----
    #pragma unroll
    for (int off = 16; off; off >>= 1) {
        Fx += __shfl_down_sync(FULL, Fx, off);
        Fy += __shfl_down_sync(FULL, Fy, off);
        d3 += __shfl_down_sync(FULL, d3, off);
        d4 += __shfl_down_sync(FULL, d4, off);
    }
    int warp = t >> 5, lane = t & 31;
    if (lane == 0) {
        s_red[warp][0] = Fx;
        s_red[warp][1] = Fy;
        s_red[warp][2] = d3;
        s_red[warp][3] = d4;
    }
    __syncthreads();

    if (t == 0) {
        float fx = 0.f, fy = 0.f, s3 = 0.f, s4 = 0.f;
        #pragma unroll
        for (int w = 0; w < 4; w++) {
            fx += s_red[w][0];
            fy += s_red[w][1];
            s3 += s_red[w][2];
            s4 += s_red[w][3];
        }
        float Ma = s3 * (0.3f / (float)NODES) + 0.3f;
        float af = s4 * (ALPHA_F / (float)NODES);
        float ca = cosf(af), sa = sinf(af);
        float Fxn = fx * ca + fy * sa;
        float Fyn = fy * ca - Fxn * sa;   // reference uses Fx_new here (literal)
        float q = QCOEF_F * Ma * Ma;
        out[c] = make_float2(Fxn / q, Fyn / q);
    }
}

extern "C" void kernel_launch(void* const* d_in, const int* in_sizes, int n_in,
                              void* d_out, int out_size) {
    // metadata order: batch(int32), coords(f32), fields(f32), design(f32), num_case, nodes_num
    const float* coords = (const float*)d_in[1];
    const float* fields = (const float*)d_in[2];
    const float* design = (const float*)d_in[3];
    float2* out = (float2*)d_out;
    dyn_kernel<<<NUMCASE, 128>>>(coords, fields, design, out);
}

// round 6
// speedup vs baseline: 1.0952x; 1.0238x over previous
#include <cuda_runtime.h>

#define NODES 336
#define NPC   8192
#define NUMCASE 2048
#define MIU_F 1.9e-05f
#define ALPHA_F 0.10471975511965977f   // 6*pi/180
#define QCOEF_F 73830.75f              // 0.5*1.225*ACOUSTIC^2
#define FULL 0xffffffffu

// 2 cases per CTA: grid = 1024 -> single perfectly-balanced wave on 148 SMs.
__global__ __launch_bounds__(128, 8) void dyn_kernel(
    const float* __restrict__ coords,
    const float* __restrict__ fields,
    const float* __restrict__ design,
    float2* __restrict__ out)
{
    const int c0 = blockIdx.x * 2;
    const int t = threadIdx.x;

    __shared__ float2 s_n0[2][NODES];
    __shared__ float2 s_f1[2][NODES];   // (u, v)
    __shared__ float  s_dl[2][NODES];   // delta
    __shared__ float  s_red[4][8];

    float2 n0[2][3];
    float pt[2][3];
    float d3[2] = {0.f, 0.f}, d4[2] = {0.f, 0.f};

    const float2* cf2 = (const float2*)coords;
    const float4* ff4 = (const float4*)fields;

    // ---- Phase 0: front-batched loads for BOTH cases (max MLP), stage smem ----
    #pragma unroll
    for (int cc = 0; cc < 2; cc++) {
        const int base = (c0 + cc) * NPC;
        #pragma unroll
        for (int k = 0; k < 3; k++) {
            int j = t + k * 128;
            bool valid = (k < 2) || (t < NODES - 256);
            if (valid) {
                float2 a = cf2[base + j];
                float2 b = cf2[base + NODES + j];
                float4 f1 = ff4[base + NODES + j];
                n0[cc][k] = a;
                pt[cc][k] = fields[4 * (base + j)];       // f0[:, :, 0]
                d3[cc] += design[5 * (base + j) + 3];
                d4[cc] += design[5 * (base + j) + 4];
                s_n0[cc][j] = a;
                s_f1[cc][j] = make_float2(f1.z, f1.w);
                float dx = b.x - a.x, dy = b.y - a.y;
                s_dl[cc][j] = sqrtf(dx * dx + dy * dy);
            }
        }
    }
    __syncthreads();

    // ---- Phase 1: tau[j], tau[j+1] recomputed locally; accumulate forces ----
    float Fx[2] = {0.f, 0.f}, Fy[2] = {0.f, 0.f};
    #pragma unroll
    for (int cc = 0; cc < 2; cc++) {
        #pragma unroll
        for (int k = 0; k < 3; k++) {
            int j = t + k * 128;
            bool valid = (k < 2) || (t < NODES - 256);
            if (valid) {
                int jp  = (j + 1 == NODES) ? 0 : j + 1;
                int jpp = (jp + 1 == NODES) ? 0 : jp + 1;
                float2 a  = n0[cc][k];
                float2 b  = s_n0[cc][jp];
                float2 cn = s_n0[cc][jpp];
                float tx = b.x - a.x, ty = b.y - a.y;
                float tn = sqrtf(tx * tx + ty * ty);
                float2 f = s_f1[cc][j];
                float tau0 = MIU_F * ((f.x * tx + f.y * ty) / tn) / s_dl[cc][j];
                float tx1 = cn.x - b.x, ty1 = cn.y - b.y;
                float tn1 = sqrtf(tx1 * tx1 + ty1 * ty1);
                float2 fn = s_f1[cc][jp];
                float tau1 = MIU_F * ((fn.x * tx1 + fn.y * ty1) / tn1) / s_dl[cc][jp];
                float ta = 0.5f * (tau0 + tau1);
                Fx[cc] += -pt[cc][k] * ty + 50.f * ta * tx;
                Fy[cc] +=  pt[cc][k] * tx + 50.f * ta * ty;
            }
        }
    }

    // ---- Block reduction of 8 values over 4 warps ----
    #pragma unroll
    for (int off = 16; off; off >>= 1) {
        #pragma unroll
        for (int cc = 0; cc < 2; cc++) {
            Fx[cc] += __shfl_down_sync(FULL, Fx[cc], off);
            Fy[cc] += __shfl_down_sync(FULL, Fy[cc], off);
            d3[cc] += __shfl_down_sync(FULL, d3[cc], off);
            d4[cc] += __shfl_down_sync(FULL, d4[cc], off);
        }
    }
    int warp = t >> 5, lane = t & 31;
    if (lane == 0) {
        #pragma unroll
        for (int cc = 0; cc < 2; cc++) {
            s_red[warp][4 * cc + 0] = Fx[cc];
            s_red[warp][4 * cc + 1] = Fy[cc];
            s_red[warp][4 * cc + 2] = d3[cc];
            s_red[warp][4 * cc + 3] = d4[cc];
        }
    }
    __syncthreads();

    // ---- Epilogue: threads 0 and 1 each finalize one case ----
    if (t < 2) {
        float fx = 0.f, fy = 0.f, s3 = 0.f, s4 = 0.f;
        #pragma unroll
        for (int w = 0; w < 4; w++) {
            fx += s_red[w][4 * t + 0];
            fy += s_red[w][4 * t + 1];
            s3 += s_red[w][4 * t + 2];
            s4 += s_red[w][4 * t + 3];
        }
        float Ma = s3 * (0.3f / (float)NODES) + 0.3f;
        float af = s4 * (ALPHA_F / (float)NODES);
        float ca = cosf(af), sa = sinf(af);
        float Fxn = fx * ca + fy * sa;
        float Fyn = fy * ca - Fxn * sa;   // reference uses Fx_new here (literal)
        float q = QCOEF_F * Ma * Ma;
        out[c0 + t] = make_float2(Fxn / q, Fyn / q);
    }
}

extern "C" void kernel_launch(void* const* d_in, const int* in_sizes, int n_in,
                              void* d_out, int out_size) {
    // metadata order: batch(int32), coords(f32), fields(f32), design(f32), num_case, nodes_num
    const float* coords = (const float*)d_in[1];
    const float* fields = (const float*)d_in[2];
    const float* design = (const float*)d_in[3];
    float2* out = (float2*)d_out;
    dyn_kernel<<<NUMCASE / 2, 128>>>(coords, fields, design, out);
}